// round 14
// baseline (speedup 1.0000x reference)
#include <cuda_runtime.h>
#include <cuda_fp16.h>
#include <cstdint>

// Problem constants (fixed by setup_inputs)
#define NN  50000
#define EE  800000
#define FF  64
#define HH  128
#define CC  20000
#define PP  200000
#define NFF 2048
#define LL  3

// ---------------- scratch (device globals; no allocation allowed) ----------
__device__ float g_x[NN * HH];
__device__ float g_y[NN * HH];
__device__ float g_t[NN * HH];
__device__ int   g_deg[NN];
__device__ int   g_off[NN + 1];
__device__ int   g_cur[NN];
__device__ int2  g_csr[EE];
__device__ int   g_pcnt[CC];
__device__ int   g_poff[CC + 1];
__device__ int   g_fcnt[NFF];
__device__ int   g_foff[NFF + 1];
__device__ float g_z[CC * HH];
__device__ float g_fmean[NFF * HH];
__device__ float g_hcat[CC * 2 * HH];
__device__ float g_h1[CC * HH];
__device__ float g_h2[CC * HH];
// pre-split fp16 hi/lo weight images, interleaved layout:
// per K32 chunk: [128 n][24 uint32] (16 used, permuted so each thread's two
// step-words are adjacent -> LDS.64), 12288 B/chunk; 38 chunks total.
__device__ unsigned char g_wh[466944];
__device__ unsigned char g_wl[466944];

// ---------------- fp16 split helpers ----------------------------------------
__device__ __forceinline__ void hsplit(float x, __half& h, __half& l) {
    h = __float2half(x);
    l = __float2half(x - __half2float(h));
}
__device__ __forceinline__ uint32_t pkh(__half a, __half b) {
    __half2 t = __halves2half2(a, b);   // a -> low half (lower k)
    return *reinterpret_cast<uint32_t*>(&t);
}

// interleaved word position within a chunk row: old word j (0..15, = k-pair
// index) -> pos so that (q, q+4) of each k16 step are adjacent.
__device__ __host__ __forceinline__ int wpos(int j) {
    return (j >> 3) * 8 + (j & 3) * 2 + ((j >> 2) & 1);
}

#define MMA_F16(d, a, b0, b1)                                                  \
    asm volatile(                                                              \
        "mma.sync.aligned.m16n8k16.row.col.f32.f16.f16.f32 "                   \
        "{%0,%1,%2,%3},{%4,%5,%6,%7},{%8,%9},{%0,%1,%2,%3};"                   \
        : "+f"(d[0]), "+f"(d[1]), "+f"(d[2]), "+f"(d[3])                       \
        : "r"(a[0]), "r"(a[1]), "r"(a[2]), "r"(a[3]), "r"(b0), "r"(b1))

// ---------------- weight prep: split fp16 + pack into interleaved image -----
struct PrepArgs {
    const float* W[9];
    int cum[10];
    int offB[9];
};

__global__ void prep_weights(PrepArgs pa) {
    int e = blockIdx.x * blockDim.x + threadIdx.x;
    if (e >= 155648) return;
    int w = 0;
    while (e >= pa.cum[w + 1]) w++;
    int local = e - pa.cum[w];
    int k = local >> 7, n = local & 127;
    float x = pa.W[w][(size_t)k * 128 + n];
    __half h, l;
    hsplit(x, h, l);
    int j = (k & 31) >> 1;
    uint32_t off = (uint32_t)pa.offB[w] + (uint32_t)(k >> 5) * 12288u
                 + ((uint32_t)(n * 24 + wpos(j)) << 2) + (uint32_t)(k & 1) * 2u;
    *(__half*)(g_wh + off) = h;
    *(__half*)(g_wl + off) = l;
}

// ---------------- mixed HMMA GEMM: A fp16, B fp16-split (2 MMAs/tile) -------
// out[rows,128] = act(A[rows,IN] @ W + b)
// Block 128 rows x 128 cols, 256 threads = 8 warps (4m x 2n).
// IN<=128: all B chunks staged upfront; A chunk k+1 register-prefetched.
// Interleaved 24-word rows -> every fragment fetch is one conflict-free
// LDS.64 (20 per step vs 40 LDS.32 before). __launch_bounds__(256,2).
template <int IN, int RELU>
__global__ __launch_bounds__(256, 2) void hmma_gemm(const float* __restrict__ A,
                                                    const uint32_t* __restrict__ BH,
                                                    const uint32_t* __restrict__ BL,
                                                    const float* __restrict__ bias,
                                                    float* __restrict__ out,
                                                    int rows) {
    constexpr int NCH = IN / 32;
    constexpr bool BALL = (IN <= 128);
    constexpr int CHW = 3072;                   // words per chunk image (128*24)
    constexpr int BWORDS = (BALL ? NCH : 1) * CHW;

    extern __shared__ uint32_t sm[];
    uint32_t* Bh = sm;                          // BWORDS
    uint32_t* Bl = sm + BWORDS;                 // BWORDS
    uint32_t* Ah = sm + 2 * BWORDS;             // CHW
    float* sbias = (float*)(sm + 2 * BWORDS + CHW);

    int tid = threadIdx.x, lane = tid & 31, wid = tid >> 5;
    int wm = wid >> 1, wn = wid & 1;
    int r0 = blockIdx.x * 128;

    int rb = tid >> 3;                 // base row of this thread's stage items
    int c4 = (tid & 7) * 4;            // k offset within chunk
    int kp = c4 >> 1;                  // even word index
    int p0 = wpos(kp), p1 = wpos(kp + 1);

    if (tid < 128) sbias[tid] = bias[tid];
    if (BALL) {
#pragma unroll
        for (int i = tid; i < BWORDS / 4; i += 256) {
            ((uint4*)Bh)[i] = ((const uint4*)BH)[i];
            ((uint4*)Bl)[i] = ((const uint4*)BL)[i];
        }
    }

    float acc[2][8][4];
#pragma unroll
    for (int a = 0; a < 2; a++)
#pragma unroll
        for (int b = 0; b < 8; b++)
#pragma unroll
            for (int c = 0; c < 4; c++) acc[a][b][c] = 0.f;

    // prefetch A chunk 0
    float4 v[4];
#pragma unroll
    for (int q = 0; q < 4; q++) {
        int gr = r0 + rb + q * 32;
        v[q] = (gr < rows) ? *(const float4*)(A + (size_t)gr * IN + c4)
                           : make_float4(0.f, 0.f, 0.f, 0.f);
    }

#pragma unroll 1
    for (int kt = 0; kt < NCH; kt++) {
        // ---- store prefetched A chunk as packed fp16 (interleaved pos) ----
#pragma unroll
        for (int q = 0; q < 4; q++) {
            int base = (rb + q * 32) * 24;
            Ah[base + p0] = pkh(__float2half(v[q].x), __float2half(v[q].y));
            Ah[base + p1] = pkh(__float2half(v[q].z), __float2half(v[q].w));
        }
        if (!BALL) {
            const uint4* bh4 = (const uint4*)(BH + kt * CHW);
            const uint4* bl4 = (const uint4*)(BL + kt * CHW);
#pragma unroll
            for (int i = tid; i < CHW / 4; i += 256) {
                ((uint4*)Bh)[i] = bh4[i];
                ((uint4*)Bl)[i] = bl4[i];
            }
        }
        __syncthreads();

        // ---- prefetch A chunk kt+1 (overlaps with MMA below) ----
        if (kt + 1 < NCH) {
#pragma unroll
            for (int q = 0; q < 4; q++) {
                int gr = r0 + rb + q * 32;
                v[q] = (gr < rows)
                     ? *(const float4*)(A + (size_t)gr * IN + (kt + 1) * 32 + c4)
                     : make_float4(0.f, 0.f, 0.f, 0.f);
            }
        }

        const uint32_t* bhc = Bh + (BALL ? kt * CHW : 0);
        const uint32_t* blc = Bl + (BALL ? kt * CHW : 0);
        int qb = (lane & 3) * 2;
        // ---- two k16 steps per chunk ----
#pragma unroll
        for (int s = 0; s < 2; s++) {
            int base = s * 8 + qb;
            uint32_t ah[2][4];
#pragma unroll
            for (int mt = 0; mt < 2; mt++) {
                int r = wm * 32 + mt * 16 + (lane >> 2);
                uint2 a0 = *(const uint2*)&Ah[r * 24 + base];
                uint2 a1 = *(const uint2*)&Ah[(r + 8) * 24 + base];
                ah[mt][0] = a0.x; ah[mt][1] = a1.x;
                ah[mt][2] = a0.y; ah[mt][3] = a1.y;
            }
#pragma unroll
            for (int nt = 0; nt < 8; nt++) {
                int n = wn * 64 + nt * 8 + (lane >> 2);
                uint2 bh = *(const uint2*)&bhc[n * 24 + base];
                uint2 bl = *(const uint2*)&blc[n * 24 + base];
#pragma unroll
                for (int mt = 0; mt < 2; mt++) {
                    MMA_F16(acc[mt][nt], ah[mt], bh.x, bh.y);
                    MMA_F16(acc[mt][nt], ah[mt], bl.x, bl.y);
                }
            }
        }
        __syncthreads();
    }

    // ---- epilogue: D frag rows lane>>2 (+8), cols (lane&3)*2 (+1) ----
#pragma unroll
    for (int mt = 0; mt < 2; mt++) {
#pragma unroll
        for (int nt = 0; nt < 8; nt++) {
            int col = wn * 64 + nt * 8 + (lane & 3) * 2;
            float b0 = sbias[col], b1 = sbias[col + 1];
            int row = r0 + wm * 32 + mt * 16 + (lane >> 2);
            if (row < rows) {
                float v0 = acc[mt][nt][0] + b0, v1 = acc[mt][nt][1] + b1;
                if (RELU) { v0 = fmaxf(v0, 0.f); v1 = fmaxf(v1, 0.f); }
                *(float2*)(out + (size_t)row * 128 + col) = make_float2(v0, v1);
            }
            if (row + 8 < rows) {
                float v2 = acc[mt][nt][2] + b0, v3 = acc[mt][nt][3] + b1;
                if (RELU) { v2 = fmaxf(v2, 0.f); v3 = fmaxf(v3, 0.f); }
                *(float2*)(out + (size_t)(row + 8) * 128 + col) = make_float2(v2, v3);
            }
        }
    }
}

// ---------------- fused utility kernels -------------------------------------
__global__ void zero_all_kernel() {
    int i = blockIdx.x * blockDim.x + threadIdx.x;
    if (i < NN)  g_deg[i] = 0;
    if (i < CC)  g_pcnt[i] = 0;
    if (i < NFF) g_fcnt[i] = 0;
}

__global__ void hist_all_kernel(const int* __restrict__ dst,
                                const int* __restrict__ pmem,
                                const int* __restrict__ cb) {
    int i = blockIdx.x * blockDim.x + threadIdx.x;
    if (i < EE) {
        atomicAdd(&g_deg[dst[i]], 1);
    } else if (i < EE + PP) {
        atomicAdd(&g_pcnt[pmem[i - EE]], 1);
    } else if (i < EE + PP + CC) {
        atomicAdd(&g_fcnt[cb[i - EE - PP]], 1);
    }
}

__global__ void scan_all_kernel() {
    __shared__ int sums[1024];
    const int* cnt; int n; int* off; int* cur = nullptr;
    if (blockIdx.x == 0)      { cnt = g_deg;  n = NN;  off = g_off;  cur = g_cur; }
    else if (blockIdx.x == 1) { cnt = g_pcnt; n = CC;  off = g_poff; }
    else                      { cnt = g_fcnt; n = NFF; off = g_foff; }
    int tid = threadIdx.x;
    int chunk = (n + 1023) / 1024;
    int start = tid * chunk;
    int end = start + chunk;
    if (end > n) end = n;
    int s = 0;
    for (int i = start; i < end; i++) s += cnt[i];
    sums[tid] = s;
    __syncthreads();
    for (int d = 1; d < 1024; d <<= 1) {
        int v = (tid >= d) ? sums[tid - d] : 0;
        __syncthreads();
        sums[tid] += v;
        __syncthreads();
    }
    int excl = (tid == 0) ? 0 : sums[tid - 1];
    for (int i = start; i < end; i++) {
        off[i] = excl;
        if (cur) cur[i] = excl;
        excl += cnt[i];
    }
    if (tid == 1023) off[n] = sums[1023];
}

__global__ void scatter_edges_kernel(const int* __restrict__ src,
                                     const int* __restrict__ dst,
                                     const float* __restrict__ attr) {
    int e = blockIdx.x * blockDim.x + threadIdx.x;
    if (e >= EE) return;
    int p = atomicAdd(&g_cur[dst[e]], 1);
    g_csr[p] = make_int2(src[e], __float_as_int(attr[e]));
}

// ---------------- GINE aggregation (R6-proven fp32 form) ---------------------
__global__ void aggregate_kernel(const float* __restrict__ eW,
                                 const float* __restrict__ eb) {
    int w = (blockIdx.x * blockDim.x + threadIdx.x) >> 5;
    if (w >= NN) return;
    int lane = threadIdx.x & 31;

    float4 eWv = ((const float4*)eW)[lane];
    float4 ebv = ((const float4*)eb)[lane];
    const float4* x4 = (const float4*)g_x;

    float4 acc = x4[(long long)w * 32 + lane];
    int s = g_off[w], e = g_off[w + 1];
    for (int j = s; j < e; j++) {
        int2 ed = g_csr[j];
        int src = ed.x;
        float a = __int_as_float(ed.y);
        float4 xv = x4[(long long)src * 32 + lane];
        acc.x += fmaxf(xv.x + a * eWv.x + ebv.x, 0.f);
        acc.y += fmaxf(xv.y + a * eWv.y + ebv.y, 0.f);
        acc.z += fmaxf(xv.z + a * eWv.z + ebv.z, 0.f);
        acc.w += fmaxf(xv.w + a * eWv.w + ebv.w, 0.f);
    }
    ((float4*)g_y)[(long long)w * 32 + lane] = acc;
}

// ---------------- pooling ---------------------------------------------------
__global__ void pool_mean_kernel(const int* __restrict__ pni) {
    int c = (blockIdx.x * blockDim.x + threadIdx.x) >> 5;
    if (c >= CC) return;
    int lane = threadIdx.x & 31;
    const float4* x4 = (const float4*)g_x;
    int s = g_poff[c], e = g_poff[c + 1];
    float4 acc = make_float4(0.f, 0.f, 0.f, 0.f);
    for (int p = s; p < e; p++) {
        int node = pni[p];
        float4 v = x4[(long long)node * 32 + lane];
        acc.x += v.x; acc.y += v.y; acc.z += v.z; acc.w += v.w;
    }
    int cnt = e - s;
    float inv = 1.f / (float)(cnt > 1 ? cnt : 1);
    ((float4*)g_z)[(long long)c * 32 + lane] =
        make_float4(acc.x * inv, acc.y * inv, acc.z * inv, acc.w * inv);
}

__global__ void frontier_mean_kernel() {
    int f = (blockIdx.x * blockDim.x + threadIdx.x) >> 5;
    if (f >= NFF) return;
    int lane = threadIdx.x & 31;
    const float4* z4 = (const float4*)g_z;
    int s = g_foff[f], e = g_foff[f + 1];
    float4 acc = make_float4(0.f, 0.f, 0.f, 0.f);
    for (int p = s; p < e; p++) {
        float4 v = z4[(long long)p * 32 + lane];
        acc.x += v.x; acc.y += v.y; acc.z += v.z; acc.w += v.w;
    }
    int cnt = e - s;
    float inv = 1.f / (float)(cnt > 1 ? cnt : 1);
    ((float4*)g_fmean)[(long long)f * 32 + lane] =
        make_float4(acc.x * inv, acc.y * inv, acc.z * inv, acc.w * inv);
}

__global__ void hcat_kernel(const int* __restrict__ cb) {
    int i = blockIdx.x * blockDim.x + threadIdx.x;
    if (i >= CC * HH) return;
    int c = i >> 7, h = i & 127;
    g_hcat[(long long)c * 256 + h] = g_z[i];
    g_hcat[(long long)c * 256 + 128 + h] = g_fmean[(long long)cb[c] * 128 + h];
}

__global__ void logits_kernel(const float* __restrict__ w,
                              const float* __restrict__ b,
                              float* __restrict__ out) {
    int c = (blockIdx.x * blockDim.x + threadIdx.x) >> 5;
    if (c >= CC) return;
    int lane = threadIdx.x & 31;
    float4 hv = ((const float4*)g_h2)[(long long)c * 32 + lane];
    float4 wv = ((const float4*)w)[lane];
    float s = hv.x * wv.x + hv.y * wv.y + hv.z * wv.z + hv.w * wv.w;
#pragma unroll
    for (int o = 16; o; o >>= 1) s += __shfl_xor_sync(0xffffffffu, s, o);
    if (lane == 0) out[c] = s + b[0];
}

// ---------------- host orchestration ---------------------------------------
extern "C" void kernel_launch(void* const* d_in, const int* in_sizes, int n_in,
                              void* d_out, int out_size) {
    const float* nf    = (const float*)d_in[0];
    const int*   ei    = (const int*)d_in[1];
    const float* eattr = (const float*)d_in[2];
    const int*   cb    = (const int*)d_in[4];
    const int*   pni   = (const int*)d_in[6];
    const int*   pmem  = (const int*)d_in[7];
    const float* in_W  = (const float*)d_in[8];
    const float* in_b  = (const float*)d_in[9];
    const float* e_W   = (const float*)d_in[10];
    const float* e_b   = (const float*)d_in[11];
    const float* w1    = (const float*)d_in[12];
    const float* b1    = (const float*)d_in[13];
    const float* w2    = (const float*)d_in[14];
    const float* b2    = (const float*)d_in[15];
    const float* h0W   = (const float*)d_in[16];
    const float* h0b   = (const float*)d_in[17];
    const float* h1W   = (const float*)d_in[18];
    const float* h1b   = (const float*)d_in[19];
    const float* h2W   = (const float*)d_in[20];
    const float* h2b   = (const float*)d_in[21];
    float* out = (float*)d_out;

    // dynamic SMEM: 2*BWORDS*4 (B) + 12288 (A) + 512 (bias)
    const int smem64  = (2 * 2 * 3072 + 3072 + 128) * 4;  // 61952
    const int smem128 = (2 * 4 * 3072 + 3072 + 128) * 4;  // 111104
    const int smem256 = (2 * 1 * 3072 + 3072 + 128) * 4;  // 37376
    cudaFuncSetAttribute(hmma_gemm<64, 0>,  cudaFuncAttributeMaxDynamicSharedMemorySize, smem64);
    cudaFuncSetAttribute(hmma_gemm<128, 1>, cudaFuncAttributeMaxDynamicSharedMemorySize, smem128);
    cudaFuncSetAttribute(hmma_gemm<256, 1>, cudaFuncAttributeMaxDynamicSharedMemorySize, smem256);

    float* p_x;    cudaGetSymbolAddress((void**)&p_x, g_x);
    float* p_y;    cudaGetSymbolAddress((void**)&p_y, g_y);
    float* p_t;    cudaGetSymbolAddress((void**)&p_t, g_t);
    float* p_hcat; cudaGetSymbolAddress((void**)&p_hcat, g_hcat);
    float* p_h1;   cudaGetSymbolAddress((void**)&p_h1, g_h1);
    float* p_h2;   cudaGetSymbolAddress((void**)&p_h2, g_h2);
    unsigned char* p_wh; cudaGetSymbolAddress((void**)&p_wh, g_wh);
    unsigned char* p_wl; cudaGetSymbolAddress((void**)&p_wl, g_wl);

    const int* src = ei;
    const int* dst = ei + EE;

    // weight image offsets (12288 B/chunk): inW(2), 6x conv(4), h0W(8), h1W(4)
    static const int offB[9] = {0, 24576, 73728, 122880, 172032, 221184,
                                270336, 319488, 417792};
    static const int kdim[9] = {64, 128, 128, 128, 128, 128, 128, 256, 128};
    PrepArgs pa;
    pa.W[0] = in_W;
    pa.W[1] = w1;            pa.W[2] = w2;
    pa.W[3] = w1 + 16384;    pa.W[4] = w2 + 16384;
    pa.W[5] = w1 + 32768;    pa.W[6] = w2 + 32768;
    pa.W[7] = h0W;           pa.W[8] = h1W;
    int cum = 0;
    for (int i = 0; i < 9; i++) { pa.cum[i] = cum; cum += kdim[i] * 128; pa.offB[i] = offB[i]; }
    pa.cum[9] = cum;  // 155648

    zero_all_kernel<<<(NN + 255) / 256, 256>>>();
    hist_all_kernel<<<(EE + PP + CC + 255) / 256, 256>>>(dst, pmem, cb);
    prep_weights<<<(155648 + 255) / 256, 256>>>(pa);
    // input projection (slot 4 = profiled launch)
    hmma_gemm<64, 0><<<(NN + 127) / 128, 256, smem64>>>(
        nf, (const uint32_t*)(p_wh + offB[0]), (const uint32_t*)(p_wl + offB[0]), in_b, p_x, NN);
    scan_all_kernel<<<3, 1024>>>();
    scatter_edges_kernel<<<(EE + 255) / 256, 256>>>(src, dst, eattr);

    for (int l = 0; l < LL; l++) {
        aggregate_kernel<<<(NN * 32 + 255) / 256, 256>>>(e_W, e_b);
        hmma_gemm<128, 1><<<(NN + 127) / 128, 256, smem128>>>(
            p_y, (const uint32_t*)(p_wh + offB[1 + 2 * l]), (const uint32_t*)(p_wl + offB[1 + 2 * l]),
            b1 + (size_t)l * HH, p_t, NN);
        hmma_gemm<128, 1><<<(NN + 127) / 128, 256, smem128>>>(
            p_t, (const uint32_t*)(p_wh + offB[2 + 2 * l]), (const uint32_t*)(p_wl + offB[2 + 2 * l]),
            b2 + (size_t)l * HH, p_x, NN);
    }

    pool_mean_kernel<<<(CC * 32 + 255) / 256, 256>>>(pni);
    frontier_mean_kernel<<<(NFF * 32 + 255) / 256, 256>>>();
    hcat_kernel<<<(CC * HH + 255) / 256, 256>>>(cb);
    hmma_gemm<256, 1><<<(CC + 127) / 128, 256, smem256>>>(
        p_hcat, (const uint32_t*)(p_wh + offB[7]), (const uint32_t*)(p_wl + offB[7]), h0b, p_h1, CC);
    hmma_gemm<128, 1><<<(CC + 127) / 128, 256, smem128>>>(
        p_h1, (const uint32_t*)(p_wh + offB[8]), (const uint32_t*)(p_wl + offB[8]), h1b, p_h2, CC);
    logits_kernel<<<(CC * 32 + 255) / 256, 256>>>(h2W, h2b, out);
}

// round 15
// speedup vs baseline: 1.0787x; 1.0787x over previous
#include <cuda_runtime.h>
#include <cuda_fp16.h>
#include <cstdint>

// Problem constants (fixed by setup_inputs)
#define NN  50000
#define EE  800000
#define FF  64
#define HH  128
#define CC  20000
#define PP  200000
#define NFF 2048
#define LL  3

// ---------------- scratch (device globals; no allocation allowed) ----------
__device__ float    g_x[NN * HH];
__device__ uint2    g_y16[NN * 32];      // aggregate out, fp16 half2-packed
__device__ uint2    g_t16[NN * 32];      // GEMM1 out, fp16
__device__ int      g_deg[NN];
__device__ int      g_off[NN + 1];
__device__ int      g_cur[NN];
__device__ int2     g_csr[EE];
__device__ int      g_pcnt[CC];
__device__ int      g_poff[CC + 1];
__device__ int      g_fcnt[NFF];
__device__ int      g_foff[NFF + 1];
__device__ float    g_z[CC * HH];
__device__ float    g_fmean[NFF * HH];
__device__ uint32_t g_hcat16[CC * 128];  // [z | ctx] fp16, 128 half2 words/row
__device__ uint32_t g_h1_16[CC * 64];    // h0 out, fp16
__device__ float    g_h2[CC * HH];
// pre-split fp16 hi/lo weight images (R12 layout):
// per K32 chunk: [128 n][20 uint32] (16 used, 4 pad) = 10240 B
__device__ unsigned char g_wh[389120];
__device__ unsigned char g_wl[389120];

// ---------------- fp16 split helpers ----------------------------------------
__device__ __forceinline__ void hsplit(float x, __half& h, __half& l) {
    h = __float2half(x);
    l = __float2half(x - __half2float(h));
}
__device__ __forceinline__ uint32_t pkh(__half a, __half b) {
    __half2 t = __halves2half2(a, b);   // a -> low half (lower k)
    return *reinterpret_cast<uint32_t*>(&t);
}
__device__ __forceinline__ uint32_t pkf(float a, float b) {
    return pkh(__float2half(a), __float2half(b));
}

#define MMA_F16(d, a, b0, b1)                                                  \
    asm volatile(                                                              \
        "mma.sync.aligned.m16n8k16.row.col.f32.f16.f16.f32 "                   \
        "{%0,%1,%2,%3},{%4,%5,%6,%7},{%8,%9},{%0,%1,%2,%3};"                   \
        : "+f"(d[0]), "+f"(d[1]), "+f"(d[2]), "+f"(d[3])                       \
        : "r"(a[0]), "r"(a[1]), "r"(a[2]), "r"(a[3]), "r"(b0), "r"(b1))

// ---------------- weight prep: split fp16 + pack into image layout ----------
struct PrepArgs {
    const float* W[9];
    int cum[10];
    int offB[9];
};

__global__ void prep_weights(PrepArgs pa) {
    int e = blockIdx.x * blockDim.x + threadIdx.x;
    if (e >= 155648) return;
    int w = 0;
    while (e >= pa.cum[w + 1]) w++;
    int local = e - pa.cum[w];
    int k = local >> 7, n = local & 127;
    float x = pa.W[w][(size_t)k * 128 + n];
    __half h, l;
    hsplit(x, h, l);
    uint32_t off = (uint32_t)pa.offB[w] + (uint32_t)(k >> 5) * 10240u
                 + ((uint32_t)(n * 20 + ((k & 31) >> 1)) << 2) + (uint32_t)(k & 1) * 2u;
    *(__half*)(g_wh + off) = h;
    *(__half*)(g_wl + off) = l;
}

// ---------------- mixed HMMA GEMM: A fp16, B fp16-split (2 MMAs/tile) -------
// out[rows,128] = act(A[rows,IN] @ W + b).  R12-proven skeleton.
// AH:    A stored as fp16 half2 words (stage = pure uint2 copy, no cvt).
// OUT16: output stored as fp16 half2 words (fewer STG bytes; numerics
//        identical since the consumer GEMM would round to fp16 anyway).
template <int IN, int RELU, int AH, int OUT16>
__global__ __launch_bounds__(256, 2) void hmma_gemm(const void* __restrict__ Ap,
                                                    const uint32_t* __restrict__ BH,
                                                    const uint32_t* __restrict__ BL,
                                                    const float* __restrict__ bias,
                                                    void* __restrict__ outp,
                                                    int rows) {
    constexpr int NCH = IN / 32;
    constexpr bool BALL = (IN <= 128);
    constexpr int BWORDS = (BALL ? NCH : 1) * 2560;

    extern __shared__ uint32_t sm[];
    uint32_t* Bh = sm;                          // BWORDS
    uint32_t* Bl = sm + BWORDS;                 // BWORDS
    uint32_t* Ah = sm + 2 * BWORDS;             // 2560
    float* sbias = (float*)(sm + 2 * BWORDS + 2560);

    const float*    Af  = (const float*)Ap;
    const uint32_t* A16 = (const uint32_t*)Ap;
    float*    outf  = (float*)outp;
    uint32_t* out16 = (uint32_t*)outp;

    int tid = threadIdx.x, lane = tid & 31, wid = tid >> 5;
    int wm = wid >> 1, wn = wid & 1;
    int r0 = blockIdx.x * 128;

    int rb = tid >> 3;                 // base row of this thread's stage items
    int c4 = (tid & 7) * 4;            // k offset within chunk
    int kp = c4 >> 1;

    if (tid < 128) sbias[tid] = bias[tid];
    if (BALL) {
#pragma unroll
        for (int i = tid; i < BWORDS / 4; i += 256) {
            ((uint4*)Bh)[i] = ((const uint4*)BH)[i];
            ((uint4*)Bl)[i] = ((const uint4*)BL)[i];
        }
    }

    float acc[2][8][4];
#pragma unroll
    for (int a = 0; a < 2; a++)
#pragma unroll
        for (int b = 0; b < 8; b++)
#pragma unroll
            for (int c = 0; c < 4; c++) acc[a][b][c] = 0.f;

    // prefetch A chunk 0
    float4 vf[4];
    uint2  vh[4];
#pragma unroll
    for (int q = 0; q < 4; q++) {
        int gr = r0 + rb + q * 32;
        if (AH) {
            vh[q] = (gr < rows) ? *(const uint2*)(A16 + (size_t)gr * (IN / 2) + kp)
                                : make_uint2(0u, 0u);
        } else {
            vf[q] = (gr < rows) ? *(const float4*)(Af + (size_t)gr * IN + c4)
                                : make_float4(0.f, 0.f, 0.f, 0.f);
        }
    }

#pragma unroll 1
    for (int kt = 0; kt < NCH; kt++) {
        // ---- store prefetched A chunk into SMEM ----
#pragma unroll
        for (int q = 0; q < 4; q++) {
            if (AH) {
                *(uint2*)&Ah[(rb + q * 32) * 20 + kp] = vh[q];
            } else {
                *(uint2*)&Ah[(rb + q * 32) * 20 + kp] =
                    make_uint2(pkf(vf[q].x, vf[q].y), pkf(vf[q].z, vf[q].w));
            }
        }
        if (!BALL) {
            const uint4* bh4 = (const uint4*)(BH + kt * 2560);
            const uint4* bl4 = (const uint4*)(BL + kt * 2560);
#pragma unroll
            for (int i = tid; i < 640; i += 256) {
                ((uint4*)Bh)[i] = bh4[i];
                ((uint4*)Bl)[i] = bl4[i];
            }
        }
        __syncthreads();

        // ---- prefetch A chunk kt+1 (overlaps with MMA below) ----
        if (kt + 1 < NCH) {
#pragma unroll
            for (int q = 0; q < 4; q++) {
                int gr = r0 + rb + q * 32;
                if (AH) {
                    vh[q] = (gr < rows)
                          ? *(const uint2*)(A16 + (size_t)gr * (IN / 2) + (kt + 1) * 16 + kp)
                          : make_uint2(0u, 0u);
                } else {
                    vf[q] = (gr < rows)
                          ? *(const float4*)(Af + (size_t)gr * IN + (kt + 1) * 32 + c4)
                          : make_float4(0.f, 0.f, 0.f, 0.f);
                }
            }
        }

        const uint32_t* bhc = Bh + (BALL ? kt * 2560 : 0);
        const uint32_t* blc = Bl + (BALL ? kt * 2560 : 0);
        // ---- two k16 steps per chunk ----
#pragma unroll
        for (int s = 0; s < 2; s++) {
            int kp0 = s * 8 + (lane & 3);
            uint32_t ah[2][4];
#pragma unroll
            for (int mt = 0; mt < 2; mt++) {
                int r = wm * 32 + mt * 16 + (lane >> 2);
                ah[mt][0] = Ah[r * 20 + kp0];
                ah[mt][1] = Ah[(r + 8) * 20 + kp0];
                ah[mt][2] = Ah[r * 20 + kp0 + 4];
                ah[mt][3] = Ah[(r + 8) * 20 + kp0 + 4];
            }
#pragma unroll
            for (int nt = 0; nt < 8; nt++) {
                int n = wn * 64 + nt * 8 + (lane >> 2);
                uint32_t bh0 = bhc[n * 20 + kp0], bh1 = bhc[n * 20 + kp0 + 4];
                uint32_t bl0 = blc[n * 20 + kp0], bl1 = blc[n * 20 + kp0 + 4];
#pragma unroll
                for (int mt = 0; mt < 2; mt++) {
                    MMA_F16(acc[mt][nt], ah[mt], bh0, bh1);
                    MMA_F16(acc[mt][nt], ah[mt], bl0, bl1);
                }
            }
        }
        __syncthreads();
    }

    // ---- epilogue: D frag rows lane>>2 (+8), cols (lane&3)*2 (+1) ----
#pragma unroll
    for (int mt = 0; mt < 2; mt++) {
#pragma unroll
        for (int nt = 0; nt < 8; nt++) {
            int col = wn * 64 + nt * 8 + (lane & 3) * 2;
            float b0 = sbias[col], b1 = sbias[col + 1];
            int row = r0 + wm * 32 + mt * 16 + (lane >> 2);
            if (row < rows) {
                float v0 = acc[mt][nt][0] + b0, v1 = acc[mt][nt][1] + b1;
                if (RELU) { v0 = fmaxf(v0, 0.f); v1 = fmaxf(v1, 0.f); }
                if (OUT16) out16[(size_t)row * 64 + (col >> 1)] = pkf(v0, v1);
                else *(float2*)(outf + (size_t)row * 128 + col) = make_float2(v0, v1);
            }
            if (row + 8 < rows) {
                float v2 = acc[mt][nt][2] + b0, v3 = acc[mt][nt][3] + b1;
                if (RELU) { v2 = fmaxf(v2, 0.f); v3 = fmaxf(v3, 0.f); }
                if (OUT16) out16[(size_t)(row + 8) * 64 + (col >> 1)] = pkf(v2, v3);
                else *(float2*)(outf + (size_t)(row + 8) * 128 + col) = make_float2(v2, v3);
            }
        }
    }
}

// ---------------- fused utility kernels -------------------------------------
__global__ void zero_all_kernel() {
    int i = blockIdx.x * blockDim.x + threadIdx.x;
    if (i < NN)  g_deg[i] = 0;
    if (i < CC)  g_pcnt[i] = 0;
    if (i < NFF) g_fcnt[i] = 0;
}

__global__ void hist_all_kernel(const int* __restrict__ dst,
                                const int* __restrict__ pmem,
                                const int* __restrict__ cb) {
    int i = blockIdx.x * blockDim.x + threadIdx.x;
    if (i < EE) {
        atomicAdd(&g_deg[dst[i]], 1);
    } else if (i < EE + PP) {
        atomicAdd(&g_pcnt[pmem[i - EE]], 1);
    } else if (i < EE + PP + CC) {
        atomicAdd(&g_fcnt[cb[i - EE - PP]], 1);
    }
}

__global__ void scan_all_kernel() {
    __shared__ int sums[1024];
    const int* cnt; int n; int* off; int* cur = nullptr;
    if (blockIdx.x == 0)      { cnt = g_deg;  n = NN;  off = g_off;  cur = g_cur; }
    else if (blockIdx.x == 1) { cnt = g_pcnt; n = CC;  off = g_poff; }
    else                      { cnt = g_fcnt; n = NFF; off = g_foff; }
    int tid = threadIdx.x;
    int chunk = (n + 1023) / 1024;
    int start = tid * chunk;
    int end = start + chunk;
    if (end > n) end = n;
    int s = 0;
    for (int i = start; i < end; i++) s += cnt[i];
    sums[tid] = s;
    __syncthreads();
    for (int d = 1; d < 1024; d <<= 1) {
        int v = (tid >= d) ? sums[tid - d] : 0;
        __syncthreads();
        sums[tid] += v;
        __syncthreads();
    }
    int excl = (tid == 0) ? 0 : sums[tid - 1];
    for (int i = start; i < end; i++) {
        off[i] = excl;
        if (cur) cur[i] = excl;
        excl += cnt[i];
    }
    if (tid == 1023) off[n] = sums[1023];
}

__global__ void scatter_edges_kernel(const int* __restrict__ src,
                                     const int* __restrict__ dst,
                                     const float* __restrict__ attr) {
    int e = blockIdx.x * blockDim.x + threadIdx.x;
    if (e >= EE) return;
    int p = atomicAdd(&g_cur[dst[e]], 1);
    g_csr[p] = make_int2(src[e], __float_as_int(attr[e]));
}

// ---------------- GINE aggregation (fp32 gather, fp16 output) ---------------
// y16[i] = fp16(x[i] + sum_{j->i} relu(x[src] + a*eW + eb))
// fp16 output is numerics-identical downstream: GEMM1 rounds A to fp16 anyway.
__global__ void aggregate_kernel(const float* __restrict__ eW,
                                 const float* __restrict__ eb) {
    int w = (blockIdx.x * blockDim.x + threadIdx.x) >> 5;
    if (w >= NN) return;
    int lane = threadIdx.x & 31;

    float4 eWv = ((const float4*)eW)[lane];
    float4 ebv = ((const float4*)eb)[lane];
    const float4* x4 = (const float4*)g_x;

    float4 acc = x4[(long long)w * 32 + lane];
    int s = g_off[w], e = g_off[w + 1];
    for (int j = s; j < e; j++) {
        int2 ed = g_csr[j];
        int src = ed.x;
        float a = __int_as_float(ed.y);
        float4 xv = x4[(long long)src * 32 + lane];
        acc.x += fmaxf(xv.x + a * eWv.x + ebv.x, 0.f);
        acc.y += fmaxf(xv.y + a * eWv.y + ebv.y, 0.f);
        acc.z += fmaxf(xv.z + a * eWv.z + ebv.z, 0.f);
        acc.w += fmaxf(xv.w + a * eWv.w + ebv.w, 0.f);
    }
    g_y16[(long long)w * 32 + lane] = make_uint2(pkf(acc.x, acc.y), pkf(acc.z, acc.w));
}

// ---------------- pooling ---------------------------------------------------
__global__ void pool_mean_kernel(const int* __restrict__ pni) {
    int c = (blockIdx.x * blockDim.x + threadIdx.x) >> 5;
    if (c >= CC) return;
    int lane = threadIdx.x & 31;
    const float4* x4 = (const float4*)g_x;
    int s = g_poff[c], e = g_poff[c + 1];
    float4 acc = make_float4(0.f, 0.f, 0.f, 0.f);
    for (int p = s; p < e; p++) {
        int node = pni[p];
        float4 v = x4[(long long)node * 32 + lane];
        acc.x += v.x; acc.y += v.y; acc.z += v.z; acc.w += v.w;
    }
    int cnt = e - s;
    float inv = 1.f / (float)(cnt > 1 ? cnt : 1);
    ((float4*)g_z)[(long long)c * 32 + lane] =
        make_float4(acc.x * inv, acc.y * inv, acc.z * inv, acc.w * inv);
}

__global__ void frontier_mean_kernel() {
    int f = (blockIdx.x * blockDim.x + threadIdx.x) >> 5;
    if (f >= NFF) return;
    int lane = threadIdx.x & 31;
    const float4* z4 = (const float4*)g_z;
    int s = g_foff[f], e = g_foff[f + 1];
    float4 acc = make_float4(0.f, 0.f, 0.f, 0.f);
    for (int p = s; p < e; p++) {
        float4 v = z4[(long long)p * 32 + lane];
        acc.x += v.x; acc.y += v.y; acc.z += v.z; acc.w += v.w;
    }
    int cnt = e - s;
    float inv = 1.f / (float)(cnt > 1 ? cnt : 1);
    ((float4*)g_fmean)[(long long)f * 32 + lane] =
        make_float4(acc.x * inv, acc.y * inv, acc.z * inv, acc.w * inv);
}

// hcat in fp16: row = [z (64 half2) | ctx (64 half2)]
__global__ void hcat_kernel(const int* __restrict__ cb) {
    int i = blockIdx.x * blockDim.x + threadIdx.x;
    if (i >= CC * 64) return;
    int c = i >> 6, hp = i & 63;
    float2 zv = ((const float2*)g_z)[(size_t)c * 64 + hp];
    g_hcat16[(size_t)c * 128 + hp] = pkf(zv.x, zv.y);
    float2 fv = ((const float2*)g_fmean)[(size_t)cb[c] * 64 + hp];
    g_hcat16[(size_t)c * 128 + 64 + hp] = pkf(fv.x, fv.y);
}

__global__ void logits_kernel(const float* __restrict__ w,
                              const float* __restrict__ b,
                              float* __restrict__ out) {
    int c = (blockIdx.x * blockDim.x + threadIdx.x) >> 5;
    if (c >= CC) return;
    int lane = threadIdx.x & 31;
    float4 hv = ((const float4*)g_h2)[(long long)c * 32 + lane];
    float4 wv = ((const float4*)w)[lane];
    float s = hv.x * wv.x + hv.y * wv.y + hv.z * wv.z + hv.w * wv.w;
#pragma unroll
    for (int o = 16; o; o >>= 1) s += __shfl_xor_sync(0xffffffffu, s, o);
    if (lane == 0) out[c] = s + b[0];
}

// ---------------- host orchestration ---------------------------------------
extern "C" void kernel_launch(void* const* d_in, const int* in_sizes, int n_in,
                              void* d_out, int out_size) {
    const float* nf    = (const float*)d_in[0];
    const int*   ei    = (const int*)d_in[1];
    const float* eattr = (const float*)d_in[2];
    const int*   cb    = (const int*)d_in[4];
    const int*   pni   = (const int*)d_in[6];
    const int*   pmem  = (const int*)d_in[7];
    const float* in_W  = (const float*)d_in[8];
    const float* in_b  = (const float*)d_in[9];
    const float* e_W   = (const float*)d_in[10];
    const float* e_b   = (const float*)d_in[11];
    const float* w1    = (const float*)d_in[12];
    const float* b1    = (const float*)d_in[13];
    const float* w2    = (const float*)d_in[14];
    const float* b2    = (const float*)d_in[15];
    const float* h0W   = (const float*)d_in[16];
    const float* h0b   = (const float*)d_in[17];
    const float* h1W   = (const float*)d_in[18];
    const float* h1b   = (const float*)d_in[19];
    const float* h2W   = (const float*)d_in[20];
    const float* h2b   = (const float*)d_in[21];
    float* out = (float*)d_out;

    // dynamic SMEM: 2*BWORDS*4 (B) + 10240 (A) + 512 (bias)  [R12 sizes]
    const int smem64  = 2 * 2 * 2560 * 4 + 10240 + 512;  // 51712
    const int smem128 = 2 * 4 * 2560 * 4 + 10240 + 512;  // 92672
    const int smem256 = 2 * 1 * 2560 * 4 + 10240 + 512;  // 31232
    cudaFuncSetAttribute(hmma_gemm<64, 0, 0, 0>,  cudaFuncAttributeMaxDynamicSharedMemorySize, smem64);
    cudaFuncSetAttribute(hmma_gemm<128, 1, 1, 1>, cudaFuncAttributeMaxDynamicSharedMemorySize, smem128);
    cudaFuncSetAttribute(hmma_gemm<128, 1, 1, 0>, cudaFuncAttributeMaxDynamicSharedMemorySize, smem128);
    cudaFuncSetAttribute(hmma_gemm<256, 1, 1, 1>, cudaFuncAttributeMaxDynamicSharedMemorySize, smem256);

    float* p_x;    cudaGetSymbolAddress((void**)&p_x, g_x);
    uint2* p_y16;  cudaGetSymbolAddress((void**)&p_y16, g_y16);
    uint2* p_t16;  cudaGetSymbolAddress((void**)&p_t16, g_t16);
    uint32_t* p_hcat16; cudaGetSymbolAddress((void**)&p_hcat16, g_hcat16);
    uint32_t* p_h1_16;  cudaGetSymbolAddress((void**)&p_h1_16, g_h1_16);
    float* p_h2;   cudaGetSymbolAddress((void**)&p_h2, g_h2);
    unsigned char* p_wh; cudaGetSymbolAddress((void**)&p_wh, g_wh);
    unsigned char* p_wl; cudaGetSymbolAddress((void**)&p_wl, g_wl);

    const int* src = ei;
    const int* dst = ei + EE;

    // weight image offsets: inW(2ch), 6x conv(4ch), h0W(8ch), h1W(4ch); ch=10240B
    static const int offB[9] = {0, 20480, 61440, 102400, 143360, 184320,
                                225280, 266240, 348160};
    static const int kdim[9] = {64, 128, 128, 128, 128, 128, 128, 256, 128};
    PrepArgs pa;
    pa.W[0] = in_W;
    pa.W[1] = w1;            pa.W[2] = w2;
    pa.W[3] = w1 + 16384;    pa.W[4] = w2 + 16384;
    pa.W[5] = w1 + 32768;    pa.W[6] = w2 + 32768;
    pa.W[7] = h0W;           pa.W[8] = h1W;
    int cum = 0;
    for (int i = 0; i < 9; i++) { pa.cum[i] = cum; cum += kdim[i] * 128; pa.offB[i] = offB[i]; }
    pa.cum[9] = cum;  // 155648

    zero_all_kernel<<<(NN + 255) / 256, 256>>>();
    hist_all_kernel<<<(EE + PP + CC + 255) / 256, 256>>>(dst, pmem, cb);
    prep_weights<<<(155648 + 255) / 256, 256>>>(pa);
    // input projection (slot 4 = profiled launch; AH=0 path identical to R12)
    hmma_gemm<64, 0, 0, 0><<<(NN + 127) / 128, 256, smem64>>>(
        nf, (const uint32_t*)(p_wh + offB[0]), (const uint32_t*)(p_wl + offB[0]), in_b, p_x, NN);
    scan_all_kernel<<<3, 1024>>>();
    scatter_edges_kernel<<<(EE + 255) / 256, 256>>>(src, dst, eattr);

    for (int l = 0; l < LL; l++) {
        aggregate_kernel<<<(NN * 32 + 255) / 256, 256>>>(e_W, e_b);
        hmma_gemm<128, 1, 1, 1><<<(NN + 127) / 128, 256, smem128>>>(
            p_y16, (const uint32_t*)(p_wh + offB[1 + 2 * l]), (const uint32_t*)(p_wl + offB[1 + 2 * l]),
            b1 + (size_t)l * HH, p_t16, NN);
        hmma_gemm<128, 1, 1, 0><<<(NN + 127) / 128, 256, smem128>>>(
            p_t16, (const uint32_t*)(p_wh + offB[2 + 2 * l]), (const uint32_t*)(p_wl + offB[2 + 2 * l]),
            b2 + (size_t)l * HH, p_x, NN);
    }

    pool_mean_kernel<<<(CC * 32 + 255) / 256, 256>>>(pni);
    frontier_mean_kernel<<<(NFF * 32 + 255) / 256, 256>>>();
    hcat_kernel<<<(CC * 64 + 255) / 256, 256>>>(cb);
    hmma_gemm<256, 1, 1, 1><<<(CC + 127) / 128, 256, smem256>>>(
        p_hcat16, (const uint32_t*)(p_wh + offB[7]), (const uint32_t*)(p_wl + offB[7]), h0b, p_h1_16, CC);
    hmma_gemm<128, 1, 1, 0><<<(CC + 127) / 128, 256, smem128>>>(
        p_h1_16, (const uint32_t*)(p_wh + offB[8]), (const uint32_t*)(p_wl + offB[8]), h1b, p_h2, CC);
    logits_kernel<<<(CC * 32 + 255) / 256, 256>>>(h2W, h2b, out);
}

// round 16
// speedup vs baseline: 1.1042x; 1.0236x over previous
#include <cuda_runtime.h>
#include <cuda_fp16.h>
#include <cstdint>

// Problem constants (fixed by setup_inputs)
#define NN  50000
#define EE  800000
#define FF  64
#define HH  128
#define CC  20000
#define PP  200000
#define NFF 2048
#define LL  3

// ---------------- scratch (device globals; no allocation allowed) ----------
__device__ uint2    g_x16[NN * 32];      // node state, fp16 half2-packed (256 B/row)
__device__ uint2    g_y16[NN * 32];      // aggregate out, fp16
__device__ uint2    g_t16[NN * 32];      // GEMM1 out, fp16
__device__ int      g_deg[NN];
__device__ int      g_off[NN + 1];
__device__ int      g_cur[NN];
__device__ int2     g_csr[EE];
__device__ int      g_pcnt[CC];
__device__ int      g_poff[CC + 1];
__device__ int      g_fcnt[NFF];
__device__ int      g_foff[NFF + 1];
__device__ float    g_z[CC * HH];
__device__ float    g_fmean[NFF * HH];
__device__ uint32_t g_hcat16[CC * 128];  // [z | ctx] fp16, 128 half2 words/row
__device__ uint32_t g_h1_16[CC * 64];    // h0 out, fp16
__device__ float    g_h2[CC * HH];
// pre-split fp16 hi/lo weight images (R12 layout):
// per K32 chunk: [128 n][20 uint32] (16 used, 4 pad) = 10240 B
__device__ unsigned char g_wh[389120];
__device__ unsigned char g_wl[389120];

// ---------------- fp16 split helpers ----------------------------------------
__device__ __forceinline__ void hsplit(float x, __half& h, __half& l) {
    h = __float2half(x);
    l = __float2half(x - __half2float(h));
}
__device__ __forceinline__ uint32_t pkh(__half a, __half b) {
    __half2 t = __halves2half2(a, b);   // a -> low half (lower k)
    return *reinterpret_cast<uint32_t*>(&t);
}
__device__ __forceinline__ uint32_t pkf(float a, float b) {
    return pkh(__float2half(a), __float2half(b));
}

#define MMA_F16(d, a, b0, b1)                                                  \
    asm volatile(                                                              \
        "mma.sync.aligned.m16n8k16.row.col.f32.f16.f16.f32 "                   \
        "{%0,%1,%2,%3},{%4,%5,%6,%7},{%8,%9},{%0,%1,%2,%3};"                   \
        : "+f"(d[0]), "+f"(d[1]), "+f"(d[2]), "+f"(d[3])                       \
        : "r"(a[0]), "r"(a[1]), "r"(a[2]), "r"(a[3]), "r"(b0), "r"(b1))

// ---------------- weight prep: split fp16 + pack into image layout ----------
struct PrepArgs {
    const float* W[9];
    int cum[10];
    int offB[9];
};

__global__ void prep_weights(PrepArgs pa) {
    int e = blockIdx.x * blockDim.x + threadIdx.x;
    if (e >= 155648) return;
    int w = 0;
    while (e >= pa.cum[w + 1]) w++;
    int local = e - pa.cum[w];
    int k = local >> 7, n = local & 127;
    float x = pa.W[w][(size_t)k * 128 + n];
    __half h, l;
    hsplit(x, h, l);
    uint32_t off = (uint32_t)pa.offB[w] + (uint32_t)(k >> 5) * 10240u
                 + ((uint32_t)(n * 20 + ((k & 31) >> 1)) << 2) + (uint32_t)(k & 1) * 2u;
    *(__half*)(g_wh + off) = h;
    *(__half*)(g_wl + off) = l;
}

// ---------------- mixed HMMA GEMM: A fp16, B fp16-split (2 MMAs/tile) -------
// out[rows,128] = act(A[rows,IN] @ W + b).  R12-proven skeleton.
// AH:    A stored as fp16 half2 words (stage = pure uint2 copy, no cvt).
// OUT16: output stored as fp16 half2 words.
template <int IN, int RELU, int AH, int OUT16>
__global__ __launch_bounds__(256, 2) void hmma_gemm(const void* __restrict__ Ap,
                                                    const uint32_t* __restrict__ BH,
                                                    const uint32_t* __restrict__ BL,
                                                    const float* __restrict__ bias,
                                                    void* __restrict__ outp,
                                                    int rows) {
    constexpr int NCH = IN / 32;
    constexpr bool BALL = (IN <= 128);
    constexpr int BWORDS = (BALL ? NCH : 1) * 2560;

    extern __shared__ uint32_t sm[];
    uint32_t* Bh = sm;                          // BWORDS
    uint32_t* Bl = sm + BWORDS;                 // BWORDS
    uint32_t* Ah = sm + 2 * BWORDS;             // 2560
    float* sbias = (float*)(sm + 2 * BWORDS + 2560);

    const float*    Af  = (const float*)Ap;
    const uint32_t* A16 = (const uint32_t*)Ap;
    float*    outf  = (float*)outp;
    uint32_t* out16 = (uint32_t*)outp;

    int tid = threadIdx.x, lane = tid & 31, wid = tid >> 5;
    int wm = wid >> 1, wn = wid & 1;
    int r0 = blockIdx.x * 128;

    int rb = tid >> 3;                 // base row of this thread's stage items
    int c4 = (tid & 7) * 4;            // k offset within chunk
    int kp = c4 >> 1;

    if (tid < 128) sbias[tid] = bias[tid];
    if (BALL) {
#pragma unroll
        for (int i = tid; i < BWORDS / 4; i += 256) {
            ((uint4*)Bh)[i] = ((const uint4*)BH)[i];
            ((uint4*)Bl)[i] = ((const uint4*)BL)[i];
        }
    }

    float acc[2][8][4];
#pragma unroll
    for (int a = 0; a < 2; a++)
#pragma unroll
        for (int b = 0; b < 8; b++)
#pragma unroll
            for (int c = 0; c < 4; c++) acc[a][b][c] = 0.f;

    // prefetch A chunk 0
    float4 vf[4];
    uint2  vh[4];
#pragma unroll
    for (int q = 0; q < 4; q++) {
        int gr = r0 + rb + q * 32;
        if (AH) {
            vh[q] = (gr < rows) ? *(const uint2*)(A16 + (size_t)gr * (IN / 2) + kp)
                                : make_uint2(0u, 0u);
        } else {
            vf[q] = (gr < rows) ? *(const float4*)(Af + (size_t)gr * IN + c4)
                                : make_float4(0.f, 0.f, 0.f, 0.f);
        }
    }

#pragma unroll 1
    for (int kt = 0; kt < NCH; kt++) {
        // ---- store prefetched A chunk into SMEM ----
#pragma unroll
        for (int q = 0; q < 4; q++) {
            if (AH) {
                *(uint2*)&Ah[(rb + q * 32) * 20 + kp] = vh[q];
            } else {
                *(uint2*)&Ah[(rb + q * 32) * 20 + kp] =
                    make_uint2(pkf(vf[q].x, vf[q].y), pkf(vf[q].z, vf[q].w));
            }
        }
        if (!BALL) {
            const uint4* bh4 = (const uint4*)(BH + kt * 2560);
            const uint4* bl4 = (const uint4*)(BL + kt * 2560);
#pragma unroll
            for (int i = tid; i < 640; i += 256) {
                ((uint4*)Bh)[i] = bh4[i];
                ((uint4*)Bl)[i] = bl4[i];
            }
        }
        __syncthreads();

        // ---- prefetch A chunk kt+1 (overlaps with MMA below) ----
        if (kt + 1 < NCH) {
#pragma unroll
            for (int q = 0; q < 4; q++) {
                int gr = r0 + rb + q * 32;
                if (AH) {
                    vh[q] = (gr < rows)
                          ? *(const uint2*)(A16 + (size_t)gr * (IN / 2) + (kt + 1) * 16 + kp)
                          : make_uint2(0u, 0u);
                } else {
                    vf[q] = (gr < rows)
                          ? *(const float4*)(Af + (size_t)gr * IN + (kt + 1) * 32 + c4)
                          : make_float4(0.f, 0.f, 0.f, 0.f);
                }
            }
        }

        const uint32_t* bhc = Bh + (BALL ? kt * 2560 : 0);
        const uint32_t* blc = Bl + (BALL ? kt * 2560 : 0);
        // ---- two k16 steps per chunk ----
#pragma unroll
        for (int s = 0; s < 2; s++) {
            int kp0 = s * 8 + (lane & 3);
            uint32_t ah[2][4];
#pragma unroll
            for (int mt = 0; mt < 2; mt++) {
                int r = wm * 32 + mt * 16 + (lane >> 2);
                ah[mt][0] = Ah[r * 20 + kp0];
                ah[mt][1] = Ah[(r + 8) * 20 + kp0];
                ah[mt][2] = Ah[r * 20 + kp0 + 4];
                ah[mt][3] = Ah[(r + 8) * 20 + kp0 + 4];
            }
#pragma unroll
            for (int nt = 0; nt < 8; nt++) {
                int n = wn * 64 + nt * 8 + (lane >> 2);
                uint32_t bh0 = bhc[n * 20 + kp0], bh1 = bhc[n * 20 + kp0 + 4];
                uint32_t bl0 = blc[n * 20 + kp0], bl1 = blc[n * 20 + kp0 + 4];
#pragma unroll
                for (int mt = 0; mt < 2; mt++) {
                    MMA_F16(acc[mt][nt], ah[mt], bh0, bh1);
                    MMA_F16(acc[mt][nt], ah[mt], bl0, bl1);
                }
            }
        }
        __syncthreads();
    }

    // ---- epilogue: D frag rows lane>>2 (+8), cols (lane&3)*2 (+1) ----
#pragma unroll
    for (int mt = 0; mt < 2; mt++) {
#pragma unroll
        for (int nt = 0; nt < 8; nt++) {
            int col = wn * 64 + nt * 8 + (lane & 3) * 2;
            float b0 = sbias[col], b1 = sbias[col + 1];
            int row = r0 + wm * 32 + mt * 16 + (lane >> 2);
            if (row < rows) {
                float v0 = acc[mt][nt][0] + b0, v1 = acc[mt][nt][1] + b1;
                if (RELU) { v0 = fmaxf(v0, 0.f); v1 = fmaxf(v1, 0.f); }
                if (OUT16) out16[(size_t)row * 64 + (col >> 1)] = pkf(v0, v1);
                else *(float2*)(outf + (size_t)row * 128 + col) = make_float2(v0, v1);
            }
            if (row + 8 < rows) {
                float v2 = acc[mt][nt][2] + b0, v3 = acc[mt][nt][3] + b1;
                if (RELU) { v2 = fmaxf(v2, 0.f); v3 = fmaxf(v3, 0.f); }
                if (OUT16) out16[(size_t)(row + 8) * 64 + (col >> 1)] = pkf(v2, v3);
                else *(float2*)(outf + (size_t)(row + 8) * 128 + col) = make_float2(v2, v3);
            }
        }
    }
}

// ---------------- fused utility kernels -------------------------------------
__global__ void zero_all_kernel() {
    int i = blockIdx.x * blockDim.x + threadIdx.x;
    if (i < NN)  g_deg[i] = 0;
    if (i < CC)  g_pcnt[i] = 0;
    if (i < NFF) g_fcnt[i] = 0;
}

__global__ void hist_all_kernel(const int* __restrict__ dst,
                                const int* __restrict__ pmem,
                                const int* __restrict__ cb) {
    int i = blockIdx.x * blockDim.x + threadIdx.x;
    if (i < EE) {
        atomicAdd(&g_deg[dst[i]], 1);
    } else if (i < EE + PP) {
        atomicAdd(&g_pcnt[pmem[i - EE]], 1);
    } else if (i < EE + PP + CC) {
        atomicAdd(&g_fcnt[cb[i - EE - PP]], 1);
    }
}

__global__ void scan_all_kernel() {
    __shared__ int sums[1024];
    const int* cnt; int n; int* off; int* cur = nullptr;
    if (blockIdx.x == 0)      { cnt = g_deg;  n = NN;  off = g_off;  cur = g_cur; }
    else if (blockIdx.x == 1) { cnt = g_pcnt; n = CC;  off = g_poff; }
    else                      { cnt = g_fcnt; n = NFF; off = g_foff; }
    int tid = threadIdx.x;
    int chunk = (n + 1023) / 1024;
    int start = tid * chunk;
    int end = start + chunk;
    if (end > n) end = n;
    int s = 0;
    for (int i = start; i < end; i++) s += cnt[i];
    sums[tid] = s;
    __syncthreads();
    for (int d = 1; d < 1024; d <<= 1) {
        int v = (tid >= d) ? sums[tid - d] : 0;
        __syncthreads();
        sums[tid] += v;
        __syncthreads();
    }
    int excl = (tid == 0) ? 0 : sums[tid - 1];
    for (int i = start; i < end; i++) {
        off[i] = excl;
        if (cur) cur[i] = excl;
        excl += cnt[i];
    }
    if (tid == 1023) off[n] = sums[1023];
}

__global__ void scatter_edges_kernel(const int* __restrict__ src,
                                     const int* __restrict__ dst,
                                     const float* __restrict__ attr) {
    int e = blockIdx.x * blockDim.x + threadIdx.x;
    if (e >= EE) return;
    int p = atomicAdd(&g_cur[dst[e]], 1);
    g_csr[p] = make_int2(src[e], __float_as_int(attr[e]));
}

// ---------------- GINE aggregation (fp16 gather, fp16 output) ----------------
// y16[i] = fp16(x16[i] + sum_{j->i} relu(x16[src] + a*eW + eb))
// Gather is half the bytes of fp32 (256 B/row). fp16 rounding of x terms was
// measured benign in R9 (delta ~5e-6).
__global__ void aggregate_kernel(const float* __restrict__ eW,
                                 const float* __restrict__ eb) {
    int w = (blockIdx.x * blockDim.x + threadIdx.x) >> 5;
    if (w >= NN) return;
    int lane = threadIdx.x & 31;

    float4 eWv = ((const float4*)eW)[lane];
    float4 ebv = ((const float4*)eb)[lane];

    uint2 sv = g_x16[(size_t)w * 32 + lane];
    float2 s0 = __half22float2(*(__half2*)&sv.x);
    float2 s1 = __half22float2(*(__half2*)&sv.y);
    float4 acc = make_float4(s0.x, s0.y, s1.x, s1.y);

    int s = g_off[w], e = g_off[w + 1];
    for (int j = s; j < e; j++) {
        int2 ed = g_csr[j];
        float a = __int_as_float(ed.y);
        uint2 hv = g_x16[(size_t)ed.x * 32 + lane];
        float2 f0 = __half22float2(*(__half2*)&hv.x);
        float2 f1 = __half22float2(*(__half2*)&hv.y);
        acc.x += fmaxf(f0.x + a * eWv.x + ebv.x, 0.f);
        acc.y += fmaxf(f0.y + a * eWv.y + ebv.y, 0.f);
        acc.z += fmaxf(f1.x + a * eWv.z + ebv.z, 0.f);
        acc.w += fmaxf(f1.y + a * eWv.w + ebv.w, 0.f);
    }
    g_y16[(size_t)w * 32 + lane] = make_uint2(pkf(acc.x, acc.y), pkf(acc.z, acc.w));
}

// ---------------- pooling (fp16 gather, fp32 accumulate) ---------------------
__global__ void pool_mean_kernel(const int* __restrict__ pni) {
    int c = (blockIdx.x * blockDim.x + threadIdx.x) >> 5;
    if (c >= CC) return;
    int lane = threadIdx.x & 31;
    int s = g_poff[c], e = g_poff[c + 1];
    float4 acc = make_float4(0.f, 0.f, 0.f, 0.f);
    for (int p = s; p < e; p++) {
        int node = pni[p];
        uint2 hv = g_x16[(size_t)node * 32 + lane];
        float2 f0 = __half22float2(*(__half2*)&hv.x);
        float2 f1 = __half22float2(*(__half2*)&hv.y);
        acc.x += f0.x; acc.y += f0.y; acc.z += f1.x; acc.w += f1.y;
    }
    int cnt = e - s;
    float inv = 1.f / (float)(cnt > 1 ? cnt : 1);
    ((float4*)g_z)[(long long)c * 32 + lane] =
        make_float4(acc.x * inv, acc.y * inv, acc.z * inv, acc.w * inv);
}

__global__ void frontier_mean_kernel() {
    int f = (blockIdx.x * blockDim.x + threadIdx.x) >> 5;
    if (f >= NFF) return;
    int lane = threadIdx.x & 31;
    const float4* z4 = (const float4*)g_z;
    int s = g_foff[f], e = g_foff[f + 1];
    float4 acc = make_float4(0.f, 0.f, 0.f, 0.f);
    for (int p = s; p < e; p++) {
        float4 v = z4[(long long)p * 32 + lane];
        acc.x += v.x; acc.y += v.y; acc.z += v.z; acc.w += v.w;
    }
    int cnt = e - s;
    float inv = 1.f / (float)(cnt > 1 ? cnt : 1);
    ((float4*)g_fmean)[(long long)f * 32 + lane] =
        make_float4(acc.x * inv, acc.y * inv, acc.z * inv, acc.w * inv);
}

// hcat in fp16: row = [z (64 half2) | ctx (64 half2)]
__global__ void hcat_kernel(const int* __restrict__ cb) {
    int i = blockIdx.x * blockDim.x + threadIdx.x;
    if (i >= CC * 64) return;
    int c = i >> 6, hp = i & 63;
    float2 zv = ((const float2*)g_z)[(size_t)c * 64 + hp];
    g_hcat16[(size_t)c * 128 + hp] = pkf(zv.x, zv.y);
    float2 fv = ((const float2*)g_fmean)[(size_t)cb[c] * 64 + hp];
    g_hcat16[(size_t)c * 128 + 64 + hp] = pkf(fv.x, fv.y);
}

__global__ void logits_kernel(const float* __restrict__ w,
                              const float* __restrict__ b,
                              float* __restrict__ out) {
    int c = (blockIdx.x * blockDim.x + threadIdx.x) >> 5;
    if (c >= CC) return;
    int lane = threadIdx.x & 31;
    float4 hv = ((const float4*)g_h2)[(long long)c * 32 + lane];
    float4 wv = ((const float4*)w)[lane];
    float s = hv.x * wv.x + hv.y * wv.y + hv.z * wv.z + hv.w * wv.w;
#pragma unroll
    for (int o = 16; o; o >>= 1) s += __shfl_xor_sync(0xffffffffu, s, o);
    if (lane == 0) out[c] = s + b[0];
}

// ---------------- host orchestration ---------------------------------------
extern "C" void kernel_launch(void* const* d_in, const int* in_sizes, int n_in,
                              void* d_out, int out_size) {
    const float* nf    = (const float*)d_in[0];
    const int*   ei    = (const int*)d_in[1];
    const float* eattr = (const float*)d_in[2];
    const int*   cb    = (const int*)d_in[4];
    const int*   pni   = (const int*)d_in[6];
    const int*   pmem  = (const int*)d_in[7];
    const float* in_W  = (const float*)d_in[8];
    const float* in_b  = (const float*)d_in[9];
    const float* e_W   = (const float*)d_in[10];
    const float* e_b   = (const float*)d_in[11];
    const float* w1    = (const float*)d_in[12];
    const float* b1    = (const float*)d_in[13];
    const float* w2    = (const float*)d_in[14];
    const float* b2    = (const float*)d_in[15];
    const float* h0W   = (const float*)d_in[16];
    const float* h0b   = (const float*)d_in[17];
    const float* h1W   = (const float*)d_in[18];
    const float* h1b   = (const float*)d_in[19];
    const float* h2W   = (const float*)d_in[20];
    const float* h2b   = (const float*)d_in[21];
    float* out = (float*)d_out;

    // dynamic SMEM: 2*BWORDS*4 (B) + 10240 (A) + 512 (bias)  [R12 sizes]
    const int smem64  = 2 * 2 * 2560 * 4 + 10240 + 512;  // 51712
    const int smem128 = 2 * 4 * 2560 * 4 + 10240 + 512;  // 92672
    const int smem256 = 2 * 1 * 2560 * 4 + 10240 + 512;  // 31232
    cudaFuncSetAttribute(hmma_gemm<64, 0, 0, 1>,  cudaFuncAttributeMaxDynamicSharedMemorySize, smem64);
    cudaFuncSetAttribute(hmma_gemm<128, 1, 1, 1>, cudaFuncAttributeMaxDynamicSharedMemorySize, smem128);
    cudaFuncSetAttribute(hmma_gemm<128, 1, 1, 0>, cudaFuncAttributeMaxDynamicSharedMemorySize, smem128);
    cudaFuncSetAttribute(hmma_gemm<256, 1, 1, 1>, cudaFuncAttributeMaxDynamicSharedMemorySize, smem256);

    uint2* p_x16;  cudaGetSymbolAddress((void**)&p_x16, g_x16);
    uint2* p_y16;  cudaGetSymbolAddress((void**)&p_y16, g_y16);
    uint2* p_t16;  cudaGetSymbolAddress((void**)&p_t16, g_t16);
    uint32_t* p_hcat16; cudaGetSymbolAddress((void**)&p_hcat16, g_hcat16);
    uint32_t* p_h1_16;  cudaGetSymbolAddress((void**)&p_h1_16, g_h1_16);
    float* p_h2;   cudaGetSymbolAddress((void**)&p_h2, g_h2);
    unsigned char* p_wh; cudaGetSymbolAddress((void**)&p_wh, g_wh);
    unsigned char* p_wl; cudaGetSymbolAddress((void**)&p_wl, g_wl);

    const int* src = ei;
    const int* dst = ei + EE;

    // weight image offsets: inW(2ch), 6x conv(4ch), h0W(8ch), h1W(4ch); ch=10240B
    static const int offB[9] = {0, 20480, 61440, 102400, 143360, 184320,
                                225280, 266240, 348160};
    static const int kdim[9] = {64, 128, 128, 128, 128, 128, 128, 256, 128};
    PrepArgs pa;
    pa.W[0] = in_W;
    pa.W[1] = w1;            pa.W[2] = w2;
    pa.W[3] = w1 + 16384;    pa.W[4] = w2 + 16384;
    pa.W[5] = w1 + 32768;    pa.W[6] = w2 + 32768;
    pa.W[7] = h0W;           pa.W[8] = h1W;
    int cum = 0;
    for (int i = 0; i < 9; i++) { pa.cum[i] = cum; cum += kdim[i] * 128; pa.offB[i] = offB[i]; }
    pa.cum[9] = cum;  // 155648

    zero_all_kernel<<<(NN + 255) / 256, 256>>>();
    hist_all_kernel<<<(EE + PP + CC + 255) / 256, 256>>>(dst, pmem, cb);
    prep_weights<<<(155648 + 255) / 256, 256>>>(pa);
    // input projection (slot 4 = profiled launch; writes fp16 x)
    hmma_gemm<64, 0, 0, 1><<<(NN + 127) / 128, 256, smem64>>>(
        nf, (const uint32_t*)(p_wh + offB[0]), (const uint32_t*)(p_wl + offB[0]), in_b, p_x16, NN);
    scan_all_kernel<<<3, 1024>>>();
    scatter_edges_kernel<<<(EE + 255) / 256, 256>>>(src, dst, eattr);

    for (int l = 0; l < LL; l++) {
        aggregate_kernel<<<(NN * 32 + 255) / 256, 256>>>(e_W, e_b);
        hmma_gemm<128, 1, 1, 1><<<(NN + 127) / 128, 256, smem128>>>(
            p_y16, (const uint32_t*)(p_wh + offB[1 + 2 * l]), (const uint32_t*)(p_wl + offB[1 + 2 * l]),
            b1 + (size_t)l * HH, p_t16, NN);
        hmma_gemm<128, 1, 1, 1><<<(NN + 127) / 128, 256, smem128>>>(
            p_t16, (const uint32_t*)(p_wh + offB[2 + 2 * l]), (const uint32_t*)(p_wl + offB[2 + 2 * l]),
            b2 + (size_t)l * HH, p_x16, NN);
    }

    pool_mean_kernel<<<(CC * 32 + 255) / 256, 256>>>(pni);
    frontier_mean_kernel<<<(NFF * 32 + 255) / 256, 256>>>();
    hcat_kernel<<<(CC * 64 + 255) / 256, 256>>>(cb);
    hmma_gemm<256, 1, 1, 1><<<(CC + 127) / 128, 256, smem256>>>(
        p_hcat16, (const uint32_t*)(p_wh + offB[7]), (const uint32_t*)(p_wl + offB[7]), h0b, p_h1_16, CC);
    hmma_gemm<128, 1, 1, 0><<<(CC + 127) / 128, 256, smem128>>>(
        p_h1_16, (const uint32_t*)(p_wh + offB[8]), (const uint32_t*)(p_wl + offB[8]), h1b, p_h2, CC);
    logits_kernel<<<(CC * 32 + 255) / 256, 256>>>(h2W, h2b, out);
}